// round 7
// baseline (speedup 1.0000x reference)
#include <cuda_runtime.h>
#include <cuda_bf16.h>
#include <cstdint>

// Sparsemax rows of 2048 fp32 — persistent kernel, cp.async double-buffered
// row pipeline (depth 2) into shared memory.
// Static threshold THETA: candidates z > THETA (~25/row for N(0,1)) gathered
// to shared; warp 0 solves Michelot; tau >= THETA self-certifies exactness
// (all discarded elements <= THETA <= tau => KKT). Full-block Michelot
// fallback (row re-read from smem-resident registers) keeps correctness.

#define ROWLEN  2048
#define THREADS 256
#define VPT     (ROWLEN / THREADS)   // 8
#define NWARP   (THREADS / 32)       // 8
#define F4PROW  (ROWLEN / 4)         // 512 float4 per row
#define CAP     64
#define THETA   2.25f
#define NEG_INF (-3.0e38f)
#define FULLM   0xffffffffu
#define OCC     8
#define GRID_CTAS (148 * OCC)

__device__ __forceinline__ void cp_async16(uint32_t smem_dst, const void* gsrc) {
    asm volatile("cp.async.cg.shared.global [%0], [%1], 16;"
                 :: "r"(smem_dst), "l"(gsrc) : "memory");
}
__device__ __forceinline__ void cp_commit() {
    asm volatile("cp.async.commit_group;" ::: "memory");
}
__device__ __forceinline__ void cp_wait1() {
    asm volatile("cp.async.wait_group 1;" ::: "memory");
}
__device__ __forceinline__ void cp_wait0() {
    asm volatile("cp.async.wait_group 0;" ::: "memory");
}

__global__ __launch_bounds__(THREADS, OCC)
void sparsemax_kernel(const float* __restrict__ z, float* __restrict__ out, int rows) {
    const float4* __restrict__ z4   = reinterpret_cast<const float4*>(z);
    float4* __restrict__       out4 = reinterpret_cast<float4*>(out);
    const int tid  = threadIdx.x;
    const int lane = tid & 31;
    const int wid  = tid >> 5;
    const long long stride = gridDim.x;

    __shared__ __align__(16) float buf[2][ROWLEN];
    __shared__ float s_cand[CAP];
    __shared__ int   s_n;
    __shared__ float s_tau;
    __shared__ int   s_ok;
    __shared__ float s_red[NWARP];
    __shared__ float s_cnt[NWARP];

    long long r = blockIdx.x;
    if (r >= rows) return;

    // smem u32 addresses of this thread's two float4 slots in each buffer
    uint32_t sbase;
    asm("{ .reg .u64 t; cvta.to.shared.u64 t, %1; cvt.u32.u64 %0, t; }"
        : "=r"(sbase) : "l"(&buf[0][0]));
    const uint32_t d0 = sbase + (uint32_t)(tid * 16);
    const uint32_t d1 = sbase + (uint32_t)((tid + THREADS) * 16);
    const uint32_t bufstep = (uint32_t)(ROWLEN * 4);

    if (tid == 0) s_n = 0;

    // ---- prologue: prime 2-deep pipeline ----
    cp_async16(d0, &z4[r * F4PROW + tid]);
    cp_async16(d1, &z4[r * F4PROW + THREADS + tid]);
    cp_commit();
    if (r + stride < rows) {
        cp_async16(d0 + bufstep, &z4[(r + stride) * F4PROW + tid]);
        cp_async16(d1 + bufstep, &z4[(r + stride) * F4PROW + THREADS + tid]);
        cp_commit();
    }

    int p = 0;
    #pragma unroll 1
    while (true) {
        const long long rn  = r + stride;
        const long long rn2 = r + 2 * stride;

        // ---- wait for row r's copy (tail: only one group pending) ----
        if (rn < rows) cp_wait1(); else cp_wait0();
        __syncthreads();   // buf[p] visible to all threads

        // ---- read row, gather candidates > THETA ----
        const float4* bp = reinterpret_cast<const float4*>(&buf[p][0]);
        float4 a = bp[tid];
        float4 b = bp[tid + THREADS];
        float v[VPT] = {a.x, a.y, a.z, a.w, b.x, b.y, b.z, b.w};

        float m = fmaxf(fmaxf(fmaxf(v[0], v[1]), fmaxf(v[2], v[3])),
                        fmaxf(fmaxf(v[4], v[5]), fmaxf(v[6], v[7])));
        if (m > THETA) {
            #pragma unroll
            for (int i = 0; i < VPT; i++) {
                if (v[i] > THETA) {
                    int idx = atomicAdd(&s_n, 1);
                    if (idx < CAP) s_cand[idx] = v[i];
                }
            }
        }
        __syncthreads();   // gather complete; all reads of buf[p] done

        // ---- refill the just-freed buffer with row r+2*stride ----
        if (rn2 < rows) {
            uint32_t off = (uint32_t)p * bufstep;
            cp_async16(d0 + off, &z4[rn2 * F4PROW + tid]);
            cp_async16(d1 + off, &z4[rn2 * F4PROW + THREADS + tid]);
            cp_commit();
        }

        // ---- warp 0: Michelot on candidate set; certify tau >= THETA ----
        if (wid == 0) {
            const int n = s_n;
            float c0 = (lane < n)      ? s_cand[lane]      : NEG_INF;
            float c1 = (lane + 32 < n) ? s_cand[lane + 32] : NEG_INF;
            float s0 = (c0 > NEG_INF ? c0 : 0.0f) + (c1 > NEG_INF ? c1 : 0.0f);
            #pragma unroll
            for (int o = 16; o > 0; o >>= 1) s0 += __shfl_xor_sync(FULLM, s0, o);
            float tau = (s0 - 1.0f) / (float)(n > 0 ? (n <= CAP ? n : CAP) : 1);
            int prev = -1;
            #pragma unroll 1
            for (int it = 0; it < 32; it++) {
                float s = 0.0f, cnt = 0.0f;
                bool a0 = c0 > tau, a1 = c1 > tau;
                s   += a0 ? c0 : 0.0f;    cnt += a0 ? 1.0f : 0.0f;
                s   += a1 ? c1 : 0.0f;    cnt += a1 ? 1.0f : 0.0f;
                #pragma unroll
                for (int o = 16; o > 0; o >>= 1) {
                    s   += __shfl_xor_sync(FULLM, s, o);
                    cnt += __shfl_xor_sync(FULLM, cnt, o);
                }
                if (cnt == 0.0f) break;
                tau = (s - 1.0f) / cnt;
                int k = (int)cnt;
                if (k == prev) break;
                prev = k;
            }
            if (lane == 0) {
                s_tau = tau;
                s_ok  = (n > 0 && n <= CAP && tau >= THETA) ? 1 : 0;
                s_n   = 0;   // next gather happens after next barrier pair
            }
        }
        __syncthreads();   // s_tau/s_ok visible, s_n reset

        if (s_ok) {
            // ---- fast path: coalesced streaming projection store ----
            const float tau = s_tau;
            float4 o0, o1;
            o0.x = fmaxf(v[0] - tau, 0.0f);
            o0.y = fmaxf(v[1] - tau, 0.0f);
            o0.z = fmaxf(v[2] - tau, 0.0f);
            o0.w = fmaxf(v[3] - tau, 0.0f);
            o1.x = fmaxf(v[4] - tau, 0.0f);
            o1.y = fmaxf(v[5] - tau, 0.0f);
            o1.z = fmaxf(v[6] - tau, 0.0f);
            o1.w = fmaxf(v[7] - tau, 0.0f);
            __stcs(&out4[r * F4PROW + tid],           o0);
            __stcs(&out4[r * F4PROW + THREADS + tid], o1);
        } else {
            // ---- fallback: full-block Michelot over register-resident row ----
            float tau;
            {
                float s = 0.0f;
                #pragma unroll
                for (int i = 0; i < VPT; i++) s += v[i];
                #pragma unroll
                for (int o = 16; o > 0; o >>= 1) s += __shfl_xor_sync(FULLM, s, o);
                if (lane == 0) s_red[wid] = s;
                __syncthreads();
                if (tid == 0) {
                    float tot = 0.0f;
                    #pragma unroll
                    for (int w = 0; w < NWARP; w++) tot += s_red[w];
                    s_tau = (tot - 1.0f) * (1.0f / (float)ROWLEN);
                }
                __syncthreads();
                tau = s_tau;
            }
            int k_prev = ROWLEN;
            #pragma unroll 1
            for (int it = 0; it < 64; it++) {
                float s = 0.0f, cf = 0.0f;
                #pragma unroll
                for (int i = 0; i < VPT; i++) {
                    bool act = v[i] > tau;
                    s  += act ? v[i] : 0.0f;
                    cf += act ? 1.0f : 0.0f;
                }
                #pragma unroll
                for (int o = 16; o > 0; o >>= 1) {
                    s  += __shfl_xor_sync(FULLM, s, o);
                    cf += __shfl_xor_sync(FULLM, cf, o);
                }
                if (lane == 0) { s_red[wid] = s; s_cnt[wid] = cf; }
                __syncthreads();
                if (tid == 0) {
                    float ts = 0.0f, tc = 0.0f;
                    #pragma unroll
                    for (int w = 0; w < NWARP; w++) { ts += s_red[w]; tc += s_cnt[w]; }
                    s_tau = (ts - 1.0f) / tc;
                    s_cnt[0] = tc;
                }
                __syncthreads();
                tau = s_tau;
                int k = (int)s_cnt[0];
                __syncthreads();
                if (k == k_prev) break;
                k_prev = k;
            }
            float4 o0, o1;
            o0.x = fmaxf(v[0] - tau, 0.0f);
            o0.y = fmaxf(v[1] - tau, 0.0f);
            o0.z = fmaxf(v[2] - tau, 0.0f);
            o0.w = fmaxf(v[3] - tau, 0.0f);
            o1.x = fmaxf(v[4] - tau, 0.0f);
            o1.y = fmaxf(v[5] - tau, 0.0f);
            o1.z = fmaxf(v[6] - tau, 0.0f);
            o1.w = fmaxf(v[7] - tau, 0.0f);
            out4[r * F4PROW + tid]           = o0;
            out4[r * F4PROW + THREADS + tid] = o1;
        }

        if (rn >= rows) break;
        r = rn;
        p ^= 1;
    }
}

extern "C" void kernel_launch(void* const* d_in, const int* in_sizes, int n_in,
                              void* d_out, int out_size) {
    const float* z = (const float*)d_in[0];
    float* out = (float*)d_out;
    int rows = in_sizes[0] / ROWLEN;
    int grid = GRID_CTAS < rows ? GRID_CTAS : rows;
    sparsemax_kernel<<<grid, THREADS>>>(z, out, rows);
}